// round 16
// baseline (speedup 1.0000x reference)
#include <cuda_runtime.h>
#include <cuda_fp16.h>
#include <cstdint>
#include <cstddef>

typedef unsigned long long ull;
typedef unsigned int u32;

#define BB 32
#define TT 1024
#define HH 512
#define GG 2048
#define NCTA 128            // lstm CTAs
#define GPW 256             // GLOBAL h image pitch (words): 1024B rows, line-aligned
#define SPW 260             // SMEM h image pitch (words): conflict-free fragment LDS

// ---------------- device scratch (allocations are forbidden) ----------------
__device__ __align__(16) float g_xp[(size_t)TT * GG * BB];   // x_proj[t][g][b]
__device__ __align__(16) u32 g_hpk[2][32 * GPW];             // fp16x2 h image [b][k/2]
__device__ __align__(128) unsigned g_flags[NCTA * 8];

// ---------------- helpers ----------------
__device__ __forceinline__ ull fadd2(ull a, ull b) {
    ull d; asm("add.rn.f32x2 %0, %1, %2;" : "=l"(d) : "l"(a), "l"(b)); return d;
}
__device__ __forceinline__ ull pack2(float x, float y) {
    ull d; asm("mov.b64 %0, {%1, %2};" : "=l"(d) : "f"(x), "f"(y)); return d;
}
__device__ __forceinline__ float sigm(float x) { return __fdividef(1.0f, 1.0f + __expf(-x)); }
__device__ __forceinline__ float tanh_(float x) { return 1.0f - __fdividef(2.0f, __expf(2.0f * x) + 1.0f); }

__device__ __forceinline__ u32 smem_u32(const void* p) {
    u32 a; asm("{ .reg .u64 t; cvta.to.shared.u64 t, %1; cvt.u32.u64 %0, t; }" : "=r"(a) : "l"(p)); return a;
}
__device__ __forceinline__ void cp_async16(u32 dst, const void* src) {
    asm volatile("cp.async.cg.shared.global [%0], [%1], 16;" :: "r"(dst), "l"(src));
}
__device__ __forceinline__ u32 pack_hf2(float a, float b) {
    return (u32)__half_as_ushort(__float2half_rn(a))
         | ((u32)__half_as_ushort(__float2half_rn(b)) << 16);
}
// fp16 mma m16n8k16, f32 accum (baseline sm_80)
__device__ __forceinline__ void mma16816h(float& c0, float& c1, float& c2, float& c3,
                                          u32 a0, u32 a1, u32 a2, u32 a3, u32 b0, u32 b1) {
    asm volatile(
        "mma.sync.aligned.m16n8k16.row.col.f32.f16.f16.f32 "
        "{%0,%1,%2,%3}, {%4,%5,%6,%7}, {%8,%9}, {%0,%1,%2,%3};"
        : "+f"(c0), "+f"(c1), "+f"(c2), "+f"(c3)
        : "r"(a0), "r"(a1), "r"(a2), "r"(a3), "r"(b0), "r"(b1));
}

// =========================================================================
// Kernel 1: HMMA x_proj, SINGLE-term fp16 — EXACT R15 champion (420us).
// =========================================================================
#define APITCH 36
#define PLW (128 * APITCH)

__global__ __launch_bounds__(256, 1) void xproj_kernel(
    const float* __restrict__ src, const float* __restrict__ Wih,
    const float* __restrict__ bih, const float* __restrict__ bhh,
    const int* __restrict__ lengths)
{
    extern __shared__ u32 smw[];
    u32* Ah = smw;
    u32* Bh = smw + PLW;

    const int tid = threadIdx.x;
    if (blockIdx.x == 0 && blockIdx.y == 0) {
        uint4 z = {0, 0, 0, 0};
        const int n16 = (int)(sizeof(g_hpk) / 16);
        for (int i = tid; i < n16; i += 256) ((uint4*)g_hpk)[i] = z;
        for (int i = tid; i < NCTA * 8; i += 256) g_flags[i] = 0u;
    }

    const int n0 = blockIdx.y * 128;
    if ((n0 >> 5) >= lengths[0]) return;         // whole n-tile past maxlen
    const int g0 = blockIdx.x * 128;
    const int warp = tid >> 5, lane = tid & 31;
    const int wm = warp & 3, wn = warp >> 2;
    const int g_ = lane >> 2, t_ = lane & 3;

    float C[2][8][4];
#pragma unroll
    for (int mt = 0; mt < 2; mt++)
#pragma unroll
        for (int nt = 0; nt < 8; nt++)
#pragma unroll
            for (int r = 0; r < 4; r++) C[mt][nt][r] = 0.0f;

    for (int kc = 0; kc < 8; kc++) {
        const int c0 = kc * 64;
#pragma unroll
        for (int i = 0; i < 8; i++) {
            int idx = tid + i * 256;
            int row = idx >> 4, cq = idx & 15;
            float4 w = *(const float4*)(Wih + (size_t)(g0 + row) * HH + c0 + cq * 4);
            *(uint2*)(Ah + row * APITCH + cq * 2) =
                make_uint2(pack_hf2(w.x, w.y), pack_hf2(w.z, w.w));
        }
#pragma unroll
        for (int i = 0; i < 8; i++) {
            int idx = tid + i * 256;
            int n = idx >> 4, cq = idx & 15;
            int N = n0 + n, b = N & 31, tt = N >> 5;
            float4 w = *(const float4*)(src + ((size_t)b * TT + tt) * HH + c0 + cq * 4);
            *(uint2*)(Bh + n * APITCH + cq * 2) =
                make_uint2(pack_hf2(w.x, w.y), pack_hf2(w.z, w.w));
        }
        __syncthreads();

#pragma unroll
        for (int kt = 0; kt < 4; kt++) {
            const int wbase = kt * 8 + t_;
            u32 ah[2][4];
#pragma unroll
            for (int mt = 0; mt < 2; mt++) {
                int ra = wm * 32 + mt * 16 + g_;
                ah[mt][0] = Ah[ra * APITCH + wbase];
                ah[mt][1] = Ah[(ra + 8) * APITCH + wbase];
                ah[mt][2] = Ah[ra * APITCH + wbase + 4];
                ah[mt][3] = Ah[(ra + 8) * APITCH + wbase + 4];
            }
#pragma unroll
            for (int nt = 0; nt < 8; nt++) {
                int nc = wn * 64 + nt * 8 + g_;
                u32 b0 = Bh[nc * APITCH + wbase];
                u32 b1 = Bh[nc * APITCH + wbase + 4];
#pragma unroll
                for (int mt = 0; mt < 2; mt++) {
                    mma16816h(C[mt][nt][0], C[mt][nt][1], C[mt][nt][2], C[mt][nt][3],
                              ah[mt][0], ah[mt][1], ah[mt][2], ah[mt][3], b0, b1);
                }
            }
        }
        __syncthreads();
    }

#pragma unroll
    for (int mt = 0; mt < 2; mt++) {
        int r0 = g0 + wm * 32 + mt * 16 + g_;
        int r1 = r0 + 8;
        float bs0 = bih[r0] + bhh[r0];
        float bs1 = bih[r1] + bhh[r1];
        ull bias0 = pack2(bs0, bs0), bias1 = pack2(bs1, bs1);
#pragma unroll
        for (int nt = 0; nt < 8; nt++) {
            int N = n0 + wn * 64 + nt * 8 + 2 * t_;
            int tt = N >> 5, b = N & 31;
            *(ull*)(g_xp + ((size_t)tt * GG + r0) * BB + b)
                = fadd2(pack2(C[mt][nt][0], C[mt][nt][1]), bias0);
            *(ull*)(g_xp + ((size_t)tt * GG + r1) * BB + b)
                = fadd2(pack2(C[mt][nt][2], C[mt][nt][3]), bias1);
        }
    }
}

// =========================================================================
// Kernel 2: fp16 2-term recurrence, warp-self-sufficient staging.
// Every warp: polls ALL 128 flags itself (4/lane), stages ONLY its own
// line-aligned 4KB slice, __syncwarp, MMA. No pre-MMA __syncthreads.
// =========================================================================
#define SM_RED  (32 * SPW * 4)                  // 33280
#define SM_TOT_L (SM_RED + 8 * 16 * 40 * 4)     // 53,760 B

__global__ __launch_bounds__(256, 1) void lstm_kernel(
    const int* __restrict__ lengths, const float* __restrict__ Whh,
    float* __restrict__ out)
{
    extern __shared__ char smc[];
    const u32 sb = smem_u32(smc);
    const u32* pk = (const u32*)smc;
    float* red_s = (float*)(smc + SM_RED);

    const int tid  = threadIdx.x;
    const int cta  = blockIdx.x;
    const int kw   = tid >> 5;               // warp = K chunk [kw*64, +64)
    const int lane = tid & 31;
    const int g_   = lane >> 2;
    const int t_   = lane & 3;
    const int len0 = lengths[0];             // max length (sorted desc)

    // ---- prologue: W fragments (hi, lo fp16), rows m = gate*4 + unit
    u32 Ahi[4][4], Alo[4][4];
    {
        const float* p0 = Whh + (size_t)((g_ >> 2) * HH + cta * 4 + (g_ & 3)) * HH;
        const float* p1 = p0 + (size_t)2 * HH * HH;   // rows +8 => gates 2,3
#pragma unroll
        for (int kt = 0; kt < 4; kt++) {
            int k0 = kw * 64 + kt * 16 + 2 * t_;
            float2 vv[4] = { *(const float2*)(p0 + k0), *(const float2*)(p1 + k0),
                             *(const float2*)(p0 + k0 + 8), *(const float2*)(p1 + k0 + 8) };
#pragma unroll
            for (int r = 0; r < 4; r++) {
                float hx = __half2float(__float2half_rn(vv[r].x));
                float hy = __half2float(__float2half_rn(vv[r].y));
                Ahi[kt][r] = pack_hf2(vv[r].x, vv[r].y);
                Alo[kt][r] = pack_hf2(vv[r].x - hx, vv[r].y - hy);
            }
        }
    }

    // every lane watches 4 flags (lane, lane+32, lane+64, lane+96)
    const unsigned* f0 = &g_flags[(lane +  0) * 8];
    const unsigned* f1 = &g_flags[(lane + 32) * 8];
    const unsigned* f2 = &g_flags[(lane + 64) * 8];
    const unsigned* f3 = &g_flags[(lane + 96) * 8];

    // per-warp slice staging: row = (i*32+lane)>>3, chunk = (i*32+lane)&7
    const int srow0 = lane >> 3;      // +4 per iteration
    const int schk  = lane & 7;

    // updater mapping (tid < 128): ub = batch, uu = unit
    const int ub = tid >> 2, uu = tid & 3;
    int   len = 0;
    float c_r = 0.0f, h_r = 0.0f;
    if (tid < 128) len = lengths[ub];
    const int pub_word = ub * GPW + cta * 2 + (uu >> 1);   // u32 index (pair of units)

    for (int t = 0; t < len0; t++) {
        const int p = t & 1;

        // xg prefetch (in flight during poll)
        float xg0 = 0.f, xg1 = 0.f, xg2 = 0.f, xg3 = 0.f;
        if (tid < 128) {
            const float* xp = g_xp + ((size_t)t * GG + cta * 4 + uu) * BB + ub;
            xg0 = xp[0 * HH * BB];
            xg1 = xp[1 * HH * BB];
            xg2 = xp[2 * HH * BB];
            xg3 = xp[3 * HH * BB];
        }

        // ---- per-warp FULL poll: this warp observes all 128 flags >= t
        if (t > 0) {
            unsigned v0, v1, v2, v3;
            bool wait;
            do {
                asm volatile("ld.acquire.gpu.u32 %0, [%1];" : "=r"(v0) : "l"(f0) : "memory");
                asm volatile("ld.acquire.gpu.u32 %0, [%1];" : "=r"(v1) : "l"(f1) : "memory");
                asm volatile("ld.acquire.gpu.u32 %0, [%1];" : "=r"(v2) : "l"(f2) : "memory");
                asm volatile("ld.acquire.gpu.u32 %0, [%1];" : "=r"(v3) : "l"(f3) : "memory");
                unsigned mn = min(min(v0, v1), min(v2, v3));
                wait = __any_sync(0xFFFFFFFFu, mn < (unsigned)t);
            } while (wait);
        }

        // ---- per-warp slice stage: own 4KB, line-aligned, 8x512B coalesced
        {
            const u32* gsrc = g_hpk[p];
#pragma unroll
            for (int i = 0; i < 8; i++) {
                int row = srow0 + i * 4;
                cp_async16(sb + (u32)(row * SPW + kw * 32 + schk * 4) * 4u,
                           gsrc + (size_t)row * GPW + kw * 32 + schk * 4);
            }
            asm volatile("cp.async.commit_group;\ncp.async.wait_group 0;" ::: "memory");
            __syncwarp();
        }

        // ---- 2-term MMA: 32 mma per warp on own slice
        float C[4][4];
#pragma unroll
        for (int nt = 0; nt < 4; nt++)
#pragma unroll
            for (int r = 0; r < 4; r++) C[nt][r] = 0.0f;

#pragma unroll
        for (int kt = 0; kt < 4; kt++) {
            const int wbase = kw * 32 + kt * 8 + t_;
#pragma unroll
            for (int nt = 0; nt < 4; nt++) {
                const int n = nt * 8 + g_;
                u32 b0 = pk[n * SPW + wbase];
                u32 b1 = pk[n * SPW + wbase + 4];
                mma16816h(C[nt][0], C[nt][1], C[nt][2], C[nt][3],
                          Ahi[kt][0], Ahi[kt][1], Ahi[kt][2], Ahi[kt][3], b0, b1);
                mma16816h(C[nt][0], C[nt][1], C[nt][2], C[nt][3],
                          Alo[kt][0], Alo[kt][1], Alo[kt][2], Alo[kt][3], b0, b1);
            }
        }

        // write k-partials: red[kw][m][40]
        {
            float* rw = red_s + kw * 16 * 40;
#pragma unroll
            for (int nt = 0; nt < 4; nt++) {
                int n = nt * 8 + 2 * t_;
                *(float2*)(rw + g_ * 40 + n)       = make_float2(C[nt][0], C[nt][1]);
                *(float2*)(rw + (g_ + 8) * 40 + n) = make_float2(C[nt][2], C[nt][3]);
            }
        }
        __syncthreads();   // all warps done (each observed all flags >= t)

        // updaters: reduce 8 k-partials, gates, state, paired fp16 publish
        if (tid < 128) {
            float s[4];
#pragma unroll
            for (int gt = 0; gt < 4; gt++) {
                int m = gt * 4 + uu;
                float a0 = 0.f, a1 = 0.f;
#pragma unroll
                for (int w = 0; w < 8; w += 2) {
                    a0 += red_s[(w * 16 + m) * 40 + ub];
                    a1 += red_s[((w + 1) * 16 + m) * 40 + ub];
                }
                s[gt] = a0 + a1;
            }
            float gi_ = sigm(xg0 + s[0]);
            float gf  = sigm(xg1 + s[1]);
            float gg  = tanh_(xg2 + s[2]);
            float go  = sigm(xg3 + s[3]);
            float cn = gf * c_r + gi_ * gg;
            float hn = go * tanh_(cn);
            bool valid = (t < len);
            if (valid) { c_r = cn; h_r = hn; }
            float out_val = valid ? hn : 0.0f;

            // fp16 publish: pair units via shuffle, even-uu lane stores one u32
            u32 hb = (u32)__half_as_ushort(__float2half_rn(h_r));
            u32 pb = __shfl_down_sync(0xFFFFFFFFu, hb, 1);
            if ((uu & 1) == 0)
                g_hpk[1 - p][pub_word] = hb | (pb << 16);

            // updater-warps-only barrier, then release (MMA warps not held)
            asm volatile("bar.sync 1, 128;" ::: "memory");
            if (tid == 0) {
                asm volatile("st.release.gpu.u32 [%0], %1;"
                             :: "l"(&g_flags[cta * 8]), "r"((unsigned)(t + 1)) : "memory");
            }
            out[((size_t)t * BB + ub) * HH + cta * 4 + uu] = out_val;
        }
    }

    // zero the out tail (t >= maxlen): pad region of pad_packed output
    for (int t = len0 + (tid >> 7); t < TT; t += 2) {
        int r = tid & 127;
        out[((size_t)t * BB + (r >> 2)) * HH + cta * 4 + (r & 3)] = 0.0f;
    }

    // final hT, cT
    if (tid < 128) {
        size_t base = (size_t)TT * BB * HH;
        out[base + (size_t)ub * HH + cta * 4 + uu] = h_r;
        out[base + (size_t)BB * HH + (size_t)ub * HH + cta * 4 + uu] = c_r;
    }
}

// =========================================================================
extern "C" void kernel_launch(void* const* d_in, const int* in_sizes, int n_in,
                              void* d_out, int out_size) {
    const float* src  = (const float*)d_in[0];
    const int*   lens = (const int*)d_in[1];
    const float* Wih  = (const float*)d_in[2];
    const float* Whh  = (const float*)d_in[3];
    const float* bih  = (const float*)d_in[4];
    const float* bhh  = (const float*)d_in[5];
    float* out = (float*)d_out;

    const int smem_xproj = 2 * PLW * 4;          // 36,864 B
    cudaFuncSetAttribute(xproj_kernel, cudaFuncAttributeMaxDynamicSharedMemorySize, smem_xproj);
    cudaFuncSetAttribute(lstm_kernel,  cudaFuncAttributeMaxDynamicSharedMemorySize, SM_TOT_L);

    dim3 grid(16, 256);
    xproj_kernel<<<grid, 256, smem_xproj>>>(src, Wih, bih, bhh, lens);
    lstm_kernel<<<NCTA, 256, SM_TOT_L>>>(lens, Whh, out);
}

// round 17
// speedup vs baseline: 1.2904x; 1.2904x over previous
#include <cuda_runtime.h>
#include <cuda_fp16.h>
#include <cstdint>
#include <cstddef>

typedef unsigned long long ull;
typedef unsigned int u32;

#define BB 32
#define TT 1024
#define HH 512
#define GG 2048
#define NCTA 128            // lstm CTAs
#define GPW 256             // GLOBAL h image pitch (words): 1024B rows, line-aligned
#define SPW 260             // SMEM h image pitch (words): conflict-free fragment LDS

// ---------------- device scratch (allocations are forbidden) ----------------
__device__ __align__(16) float g_xp[(size_t)TT * GG * BB];   // x_proj[t][g][b]
__device__ __align__(16) u32 g_hpk[2][32 * GPW];             // fp16x2 h image [b][k/2]
__device__ __align__(128) unsigned g_flags[NCTA * 8];

// ---------------- helpers ----------------
__device__ __forceinline__ ull fadd2(ull a, ull b) {
    ull d; asm("add.rn.f32x2 %0, %1, %2;" : "=l"(d) : "l"(a), "l"(b)); return d;
}
__device__ __forceinline__ ull pack2(float x, float y) {
    ull d; asm("mov.b64 %0, {%1, %2};" : "=l"(d) : "f"(x), "f"(y)); return d;
}
__device__ __forceinline__ float sigm(float x) { return __fdividef(1.0f, 1.0f + __expf(-x)); }
__device__ __forceinline__ float tanh_(float x) { return 1.0f - __fdividef(2.0f, __expf(2.0f * x) + 1.0f); }

__device__ __forceinline__ u32 smem_u32(const void* p) {
    u32 a; asm("{ .reg .u64 t; cvta.to.shared.u64 t, %1; cvt.u32.u64 %0, t; }" : "=r"(a) : "l"(p)); return a;
}
__device__ __forceinline__ void cp_async16(u32 dst, const void* src) {
    asm volatile("cp.async.cg.shared.global [%0], [%1], 16;" :: "r"(dst), "l"(src));
}
__device__ __forceinline__ u32 pack_hf2(float a, float b) {
    return (u32)__half_as_ushort(__float2half_rn(a))
         | ((u32)__half_as_ushort(__float2half_rn(b)) << 16);
}
// fp16 mma m16n8k16, f32 accum (baseline sm_80)
__device__ __forceinline__ void mma16816h(float& c0, float& c1, float& c2, float& c3,
                                          u32 a0, u32 a1, u32 a2, u32 a3, u32 b0, u32 b1) {
    asm volatile(
        "mma.sync.aligned.m16n8k16.row.col.f32.f16.f16.f32 "
        "{%0,%1,%2,%3}, {%4,%5,%6,%7}, {%8,%9}, {%0,%1,%2,%3};"
        : "+f"(c0), "+f"(c1), "+f"(c2), "+f"(c3)
        : "r"(a0), "r"(a1), "r"(a2), "r"(a3), "r"(b0), "r"(b1));
}

// =========================================================================
// Kernel 1: HMMA x_proj, SINGLE-term fp16 — EXACT R15 champion (420us).
// =========================================================================
#define APITCH 36
#define PLW (128 * APITCH)

__global__ __launch_bounds__(256, 1) void xproj_kernel(
    const float* __restrict__ src, const float* __restrict__ Wih,
    const float* __restrict__ bih, const float* __restrict__ bhh,
    const int* __restrict__ lengths)
{
    extern __shared__ u32 smw[];
    u32* Ah = smw;
    u32* Bh = smw + PLW;

    const int tid = threadIdx.x;
    if (blockIdx.x == 0 && blockIdx.y == 0) {
        uint4 z = {0, 0, 0, 0};
        const int n16 = (int)(sizeof(g_hpk) / 16);
        for (int i = tid; i < n16; i += 256) ((uint4*)g_hpk)[i] = z;
        for (int i = tid; i < NCTA * 8; i += 256) g_flags[i] = 0u;
    }

    const int n0 = blockIdx.y * 128;
    if ((n0 >> 5) >= lengths[0]) return;         // whole n-tile past maxlen
    const int g0 = blockIdx.x * 128;
    const int warp = tid >> 5, lane = tid & 31;
    const int wm = warp & 3, wn = warp >> 2;
    const int g_ = lane >> 2, t_ = lane & 3;

    float C[2][8][4];
#pragma unroll
    for (int mt = 0; mt < 2; mt++)
#pragma unroll
        for (int nt = 0; nt < 8; nt++)
#pragma unroll
            for (int r = 0; r < 4; r++) C[mt][nt][r] = 0.0f;

    for (int kc = 0; kc < 8; kc++) {
        const int c0 = kc * 64;
#pragma unroll
        for (int i = 0; i < 8; i++) {
            int idx = tid + i * 256;
            int row = idx >> 4, cq = idx & 15;
            float4 w = *(const float4*)(Wih + (size_t)(g0 + row) * HH + c0 + cq * 4);
            *(uint2*)(Ah + row * APITCH + cq * 2) =
                make_uint2(pack_hf2(w.x, w.y), pack_hf2(w.z, w.w));
        }
#pragma unroll
        for (int i = 0; i < 8; i++) {
            int idx = tid + i * 256;
            int n = idx >> 4, cq = idx & 15;
            int N = n0 + n, b = N & 31, tt = N >> 5;
            float4 w = *(const float4*)(src + ((size_t)b * TT + tt) * HH + c0 + cq * 4);
            *(uint2*)(Bh + n * APITCH + cq * 2) =
                make_uint2(pack_hf2(w.x, w.y), pack_hf2(w.z, w.w));
        }
        __syncthreads();

#pragma unroll
        for (int kt = 0; kt < 4; kt++) {
            const int wbase = kt * 8 + t_;
            u32 ah[2][4];
#pragma unroll
            for (int mt = 0; mt < 2; mt++) {
                int ra = wm * 32 + mt * 16 + g_;
                ah[mt][0] = Ah[ra * APITCH + wbase];
                ah[mt][1] = Ah[(ra + 8) * APITCH + wbase];
                ah[mt][2] = Ah[ra * APITCH + wbase + 4];
                ah[mt][3] = Ah[(ra + 8) * APITCH + wbase + 4];
            }
#pragma unroll
            for (int nt = 0; nt < 8; nt++) {
                int nc = wn * 64 + nt * 8 + g_;
                u32 b0 = Bh[nc * APITCH + wbase];
                u32 b1 = Bh[nc * APITCH + wbase + 4];
#pragma unroll
                for (int mt = 0; mt < 2; mt++) {
                    mma16816h(C[mt][nt][0], C[mt][nt][1], C[mt][nt][2], C[mt][nt][3],
                              ah[mt][0], ah[mt][1], ah[mt][2], ah[mt][3], b0, b1);
                }
            }
        }
        __syncthreads();
    }

#pragma unroll
    for (int mt = 0; mt < 2; mt++) {
        int r0 = g0 + wm * 32 + mt * 16 + g_;
        int r1 = r0 + 8;
        float bs0 = bih[r0] + bhh[r0];
        float bs1 = bih[r1] + bhh[r1];
        ull bias0 = pack2(bs0, bs0), bias1 = pack2(bs1, bs1);
#pragma unroll
        for (int nt = 0; nt < 8; nt++) {
            int N = n0 + wn * 64 + nt * 8 + 2 * t_;
            int tt = N >> 5, b = N & 31;
            *(ull*)(g_xp + ((size_t)tt * GG + r0) * BB + b)
                = fadd2(pack2(C[mt][nt][0], C[mt][nt][1]), bias0);
            *(ull*)(g_xp + ((size_t)tt * GG + r1) * BB + b)
                = fadd2(pack2(C[mt][nt][2], C[mt][nt][3]), bias1);
        }
    }
}

// =========================================================================
// Kernel 2: fp16 2-term recurrence — champion structure + active-length
// work skipping. Frozen rows keep stale (exact) h in smem; stage/MMA/gates
// shrink as batches freeze. Sync structure identical to the 2700us champion.
// =========================================================================
#define SM_RED   (32 * SPW * 4)                 // 33280
#define SM_NACT  (SM_RED + 8 * 16 * 40 * 4)     // 53760
#define SM_TOT_L (SM_NACT + 16)                 // 53776

__global__ __launch_bounds__(256, 1) void lstm_kernel(
    const int* __restrict__ lengths, const float* __restrict__ Whh,
    float* __restrict__ out)
{
    extern __shared__ char smc[];
    const u32 sb = smem_u32(smc);
    const u32* pk = (const u32*)smc;
    float* red_s = (float*)(smc + SM_RED);
    int* nact_s = (int*)(smc + SM_NACT);

    const int tid  = threadIdx.x;
    const int cta  = blockIdx.x;
    const int kw   = tid >> 5;               // warp = K chunk [kw*64, +64)
    const int lane = tid & 31;
    const int g_   = lane >> 2;
    const int t_   = lane & 3;
    const int len0 = lengths[0];             // max length (sorted desc)

    // ---- prologue: W fragments (hi, lo fp16), rows m = gate*4 + unit
    u32 Ahi[4][4], Alo[4][4];
    {
        const float* p0 = Whh + (size_t)((g_ >> 2) * HH + cta * 4 + (g_ & 3)) * HH;
        const float* p1 = p0 + (size_t)2 * HH * HH;   // rows +8 => gates 2,3
#pragma unroll
        for (int kt = 0; kt < 4; kt++) {
            int k0 = kw * 64 + kt * 16 + 2 * t_;
            float2 vv[4] = { *(const float2*)(p0 + k0), *(const float2*)(p1 + k0),
                             *(const float2*)(p0 + k0 + 8), *(const float2*)(p1 + k0 + 8) };
#pragma unroll
            for (int r = 0; r < 4; r++) {
                float hx = __half2float(__float2half_rn(vv[r].x));
                float hy = __half2float(__float2half_rn(vv[r].y));
                Ahi[kt][r] = pack_hf2(vv[r].x, vv[r].y);
                Alo[kt][r] = pack_hf2(vv[r].x - hx, vv[r].y - hy);
            }
        }
    }

    // updater mapping (tid < 128): ub = batch, uu = unit
    const int ub = tid >> 2, uu = tid & 3;
    int   len = 0;
    float c_r = 0.0f, h_r = 0.0f;
    if (tid < 128) len = lengths[ub];
    const int pub_word = ub * GPW + cta * 2 + (uu >> 1);   // u32 index (pair of units)

    int nact_p = 32;                         // thread 255's private tracker

    for (int t = 0; t < len0; t++) {
        const int p = t & 1;

        // thread 255 maintains nact(t-1) = #{len > t-1} (sorted desc)
        if (tid == 255) {
            while (nact_p > 0 && __ldg(&lengths[nact_p - 1]) <= t - 1) nact_p--;
            *nact_s = nact_p;
        }

        // xg prefetch (in flight during poll; skip for frozen batches)
        float xg0 = 0.f, xg1 = 0.f, xg2 = 0.f, xg3 = 0.f;
        if (tid < 128 && t < len) {
            const float* xp = g_xp + ((size_t)t * GG + cta * 4 + uu) * BB + ub;
            xg0 = xp[0 * HH * BB];
            xg1 = xp[1 * HH * BB];
            xg2 = xp[2 * HH * BB];
            xg3 = xp[3 * HH * BB];
        }

        // grid barrier: all 128 CTAs published step t-1
        if (t > 0 && tid < NCTA) {
            const unsigned* f = &g_flags[tid * 8];
            unsigned v;
            do {
                asm volatile("ld.acquire.gpu.u32 %0, [%1];" : "=r"(v) : "l"(f) : "memory");
            } while (v < (unsigned)t);
        }
        __syncthreads();

        const int nact = *nact_s;            // active rows bound (conservative)
        const int ntA  = (nact + 7) >> 3;    // active n-tiles for MMA

        // stage h image: only rows < nact (frozen rows stay stale == exact)
        const u32* hsrc = g_hpk[p];
#pragma unroll
        for (int i = 0; i < 8; i++) {
            int idx = tid + i * 256;         // 0..2047, 16B chunks
            int row = idx >> 6, col = idx & 63;
            if (row < nact)
                cp_async16(sb + (u32)(row * SPW + col * 4) * 4u,
                           hsrc + (size_t)row * GPW + col * 4);
        }
        asm volatile("cp.async.commit_group;\ncp.async.wait_group 0;" ::: "memory");
        __syncthreads();

        // ---- 2-term MMA on active n-tiles only
        float C[4][4];
#pragma unroll
        for (int nt = 0; nt < 4; nt++)
#pragma unroll
            for (int r = 0; r < 4; r++) C[nt][r] = 0.0f;

#pragma unroll
        for (int kt = 0; kt < 4; kt++) {
            const int wbase = kw * 32 + kt * 8 + t_;
#pragma unroll
            for (int nt = 0; nt < 4; nt++) {
                if (nt < ntA) {
                    const int n = nt * 8 + g_;
                    u32 b0 = pk[n * SPW + wbase];
                    u32 b1 = pk[n * SPW + wbase + 4];
                    mma16816h(C[nt][0], C[nt][1], C[nt][2], C[nt][3],
                              Ahi[kt][0], Ahi[kt][1], Ahi[kt][2], Ahi[kt][3], b0, b1);
                    mma16816h(C[nt][0], C[nt][1], C[nt][2], C[nt][3],
                              Alo[kt][0], Alo[kt][1], Alo[kt][2], Alo[kt][3], b0, b1);
                }
            }
        }

        // write k-partials (active tiles only): red[kw][m][40]
        {
            float* rw = red_s + kw * 16 * 40;
#pragma unroll
            for (int nt = 0; nt < 4; nt++) {
                if (nt < ntA) {
                    int n = nt * 8 + 2 * t_;
                    *(float2*)(rw + g_ * 40 + n)       = make_float2(C[nt][0], C[nt][1]);
                    *(float2*)(rw + (g_ + 8) * 40 + n) = make_float2(C[nt][2], C[nt][3]);
                }
            }
        }
        __syncthreads();

        // updaters: reduce (active only), gates, state, paired fp16 publish
        if (tid < 128) {
            bool valid = (t < len);
            float out_val = 0.0f;
            if (valid) {
                float s[4];
#pragma unroll
                for (int gt = 0; gt < 4; gt++) {
                    int m = gt * 4 + uu;
                    float a0 = 0.f, a1 = 0.f;
#pragma unroll
                    for (int w = 0; w < 8; w += 2) {
                        a0 += red_s[(w * 16 + m) * 40 + ub];
                        a1 += red_s[((w + 1) * 16 + m) * 40 + ub];
                    }
                    s[gt] = a0 + a1;
                }
                float gi_ = sigm(xg0 + s[0]);
                float gf  = sigm(xg1 + s[1]);
                float gg  = tanh_(xg2 + s[2]);
                float go  = sigm(xg3 + s[3]);
                float cn = gf * c_r + gi_ * gg;
                float hn = go * tanh_(cn);
                c_r = cn; h_r = hn;
                out_val = hn;
            }

            // fp16 publish: pair units via shuffle, even-uu lane stores one u32
            u32 hb = (u32)__half_as_ushort(__float2half_rn(h_r));
            u32 pb = __shfl_down_sync(0xFFFFFFFFu, hb, 1);
            if ((uu & 1) == 0)
                g_hpk[1 - p][pub_word] = hb | (pb << 16);

            // updater-warps-only barrier, then release (MMA warps not held)
            asm volatile("bar.sync 1, 128;" ::: "memory");
            if (tid == 0) {
                asm volatile("st.release.gpu.u32 [%0], %1;"
                             :: "l"(&g_flags[cta * 8]), "r"((unsigned)(t + 1)) : "memory");
            }
            out[((size_t)t * BB + ub) * HH + cta * 4 + uu] = out_val;
        }
    }

    // zero the out tail (t >= maxlen): pad region of pad_packed output
    for (int t = len0 + (tid >> 7); t < TT; t += 2) {
        int r = tid & 127;
        out[((size_t)t * BB + (r >> 2)) * HH + cta * 4 + (r & 3)] = 0.0f;
    }

    // final hT, cT
    if (tid < 128) {
        size_t base = (size_t)TT * BB * HH;
        out[base + (size_t)ub * HH + cta * 4 + uu] = h_r;
        out[base + (size_t)BB * HH + (size_t)ub * HH + cta * 4 + uu] = c_r;
    }
}

// =========================================================================
extern "C" void kernel_launch(void* const* d_in, const int* in_sizes, int n_in,
                              void* d_out, int out_size) {
    const float* src  = (const float*)d_in[0];
    const int*   lens = (const int*)d_in[1];
    const float* Wih  = (const float*)d_in[2];
    const float* Whh  = (const float*)d_in[3];
    const float* bih  = (const float*)d_in[4];
    const float* bhh  = (const float*)d_in[5];
    float* out = (float*)d_out;

    const int smem_xproj = 2 * PLW * 4;          // 36,864 B
    cudaFuncSetAttribute(xproj_kernel, cudaFuncAttributeMaxDynamicSharedMemorySize, smem_xproj);
    cudaFuncSetAttribute(lstm_kernel,  cudaFuncAttributeMaxDynamicSharedMemorySize, SM_TOT_L);

    dim3 grid(16, 256);
    xproj_kernel<<<grid, 256, smem_xproj>>>(src, Wih, bih, bhh, lens);
    lstm_kernel<<<NCTA, 256, SM_TOT_L>>>(lens, Whh, out);
}